// round 9
// baseline (speedup 1.0000x reference)
#include <cuda_runtime.h>
#include <cuda_bf16.h>
#include <math.h>
#include <stdint.h>

// Problem constants
static constexpr int kB  = 64;      // batch
static constexpr int kT  = 1024;    // time steps
static constexpr int kF  = 512;     // input features
static constexpr int kU  = 1024;    // hidden units
static constexpr int k4U = 4096;    // 4*U
static constexpr int kC  = 1000;    // classes

static constexpr int NCTA = 128;    // persistent CTAs (1/SM)
static constexpr int NTHR = 256;    // 8 warps: 0-3 consumers (LSTM), 4-7 producers (xz)

// Producer K split: [0, KH) via HMMA, [KH, 512) via FFMA
static constexpr int KH   = 208;    // 13 kcg
static constexpr int KHG  = 13;     // HMMA kcg count
static constexpr int KFF  = kF - KH;            // 304
static constexpr int KFF4 = KFF / 8;            // 38 uint4 per row

// SMEM layout (u32 units within dynamic smem)
static constexpr int OFF_WRF   = 0;            // Wr fragments: 16384 u32 (64 KB)
static constexpr int OFF_WKF   = 16384;        // Wk HMMA frags: 1664 uint2 = 3328 u32
static constexpr int OFF_WKS   = 19712;        // Wk fp32 (FFMA): 304*32 = 9728 u32
static constexpr int OFF_RING  = 29440;        // xz ring: 4 x 64 x 34 fp32 = 8704 u32
static constexpr int OFF_BIAS  = 38144;        // 32 fp32
static constexpr int OFF_FLAGS = 38176;        // prod_done[4], cons_done[4]
static constexpr int SMEM_U32  = 38184;        // 152736 bytes

// Scratch (device globals: allocation-free per harness rules)
// x permuted to bf16 A-fragment order (HMMA part): idx = t*4096 + kcg*128 + mt*32 + lane
__device__ uint4          g_xf[(size_t)kT * 4096];      // 67 MB
// x linear bf16 [t][row][k] (FFMA part)
__device__ __nv_bfloat16  g_xl[(size_t)kT * 64 * kF];   // 64 MB
// h ping-pong, bf16, permuted into m16n8k16 A-fragment order (see R5 comment)
__device__ uint32_t g_h[2 * 32768];
// Per-group monotonic step counters. Group g = CTAs [16g,16g+16) = kcg [8g,8g+8).
__device__ unsigned g_cnt[8 * 32];

__device__ __forceinline__ uint32_t pack_bf16(float lo, float hi) {
    uint32_t r;
    asm("cvt.rn.bf16x2.f32 %0, %1, %2;" : "=r"(r) : "f"(hi), "f"(lo));
    return r;
}
__device__ __forceinline__ float tanh_fast(float x) {
    float r;
    asm("tanh.approx.f32 %0, %1;" : "=f"(r) : "f"(x));
    return r;
}
__device__ __forceinline__ float sigmoid_fast(float x) {
    return 1.f / (1.f + __expf(-x));
}
__device__ __forceinline__ void mma_bf16(float c[4], uint32_t a0, uint32_t a1,
                                         uint32_t a2, uint32_t a3,
                                         uint32_t b0, uint32_t b1) {
    asm volatile(
        "mma.sync.aligned.m16n8k16.row.col.f32.bf16.bf16.f32 "
        "{%0,%1,%2,%3},{%4,%5,%6,%7},{%8,%9},{%0,%1,%2,%3};"
        : "+f"(c[0]), "+f"(c[1]), "+f"(c[2]), "+f"(c[3])
        : "r"(a0), "r"(a1), "r"(a2), "r"(a3), "r"(b0), "r"(b1));
}
__device__ __forceinline__ void bar_named(int id, int cnt) {
    asm volatile("bar.sync %0, %1;" :: "r"(id), "r"(cnt) : "memory");
}
__device__ __forceinline__ float bf_lo(uint32_t v) {
    return __uint_as_float(v << 16);
}
__device__ __forceinline__ float bf_hi(uint32_t v) {
    return __uint_as_float(v & 0xffff0000u);
}
// Warp-cooperative group-counter poll (consumer warps). Lanes 0-7 own counters.
__device__ __forceinline__ unsigned poll_groups(int lane, unsigned tgt,
                                                unsigned rdy) {
    unsigned ok = 1u;
    if (lane < 8 && !((rdy >> lane) & 1u)) {
        unsigned v;
        asm volatile("ld.acquire.gpu.u32 %0, [%1];"
                     : "=r"(v) : "l"(&g_cnt[lane * 32]) : "memory");
        ok = (v >= tgt) ? 1u : 0u;
    }
    return __ballot_sync(0xffffffffu, ok != 0u);
}

// ---------------------------------------------------------------------------
// Kernel 0: reset
// ---------------------------------------------------------------------------
__global__ void reset_kernel() {
    int idx = blockIdx.x * blockDim.x + threadIdx.x;
    if (idx < 8 * 32) g_cnt[idx] = 0u;
    for (int i = idx; i < 2 * 32768; i += gridDim.x * blockDim.x) g_h[i] = 0u;
}

// ---------------------------------------------------------------------------
// Kernel 1a: permute x -> bf16 A-fragment order (HMMA part)
// ---------------------------------------------------------------------------
__global__ __launch_bounds__(256) void permute_x(const float* __restrict__ x) {
    size_t idx = (size_t)blockIdx.x * 256 + threadIdx.x;   // < kT*4096
    int lane = idx & 31;
    int mt   = (idx >> 5) & 3;
    int kcg  = (idx >> 7) & 31;
    int t    = (int)(idx >> 12);
    int r  = mt * 16 + (lane >> 2);
    int k2 = kcg * 16 + 2 * (lane & 3);
    const float* x0 = x + ((size_t)r * kT + t) * kF;
    const float* x8 = x + ((size_t)(r + 8) * kT + t) * kF;
    float2 v00 = *(const float2*)(x0 + k2);
    float2 v10 = *(const float2*)(x8 + k2);
    float2 v01 = *(const float2*)(x0 + k2 + 8);
    float2 v11 = *(const float2*)(x8 + k2 + 8);
    uint4 o;
    o.x = pack_bf16(v00.x, v00.y);
    o.y = pack_bf16(v10.x, v10.y);
    o.z = pack_bf16(v01.x, v01.y);
    o.w = pack_bf16(v11.x, v11.y);
    g_xf[idx] = o;
}

// ---------------------------------------------------------------------------
// Kernel 1b: linear bf16 copy x -> g_xl[t][row][k] (FFMA part)
// ---------------------------------------------------------------------------
__global__ __launch_bounds__(256) void permute_lin(const float* __restrict__ x) {
    size_t idx = (size_t)blockIdx.x * 256 + threadIdx.x;   // < kT*64*64 (uint4)
    int k8  = idx & 63;
    int row = (idx >> 6) & 63;
    int t   = (int)(idx >> 12);
    const float* xp = x + ((size_t)row * kT + t) * kF + k8 * 8;
    float4 a = *(const float4*)xp;
    float4 b = *(const float4*)(xp + 4);
    uint4 o;
    o.x = pack_bf16(a.x, a.y);
    o.y = pack_bf16(a.z, a.w);
    o.z = pack_bf16(b.x, b.y);
    o.w = pack_bf16(b.z, b.w);
    ((uint4*)g_xl)[idx] = o;
}

// ---------------------------------------------------------------------------
// Kernel 2: fused persistent LSTM. Warps 0-3: recurrence mma + gates (as R8).
// Warps 4-7: per-step xz for this CTA's 32 cols -> SMEM ring, with K split
// across tensor pipe (K<208, HMMA) and fma pipe (K>=208, fp32 FFMA).
// ---------------------------------------------------------------------------
extern __shared__ uint32_t fsm[];

__global__ __launch_bounds__(NTHR, 1) void lstm_fused(
    const float* __restrict__ Wr, const float* __restrict__ Wk,
    const float* __restrict__ bias) {
    uint32_t*      Wr_f  = fsm + OFF_WRF;
    uint2*         Wk_f  = (uint2*)(fsm + OFF_WKF);
    float*         wk_s  = (float*)(fsm + OFF_WKS);      // [KFF][4][8]
    float*         ring  = (float*)(fsm + OFF_RING);     // [4][64][34]
    float*         bia_s = (float*)(fsm + OFF_BIAS);
    volatile int*  pflag = (volatile int*)(fsm + OFF_FLAGS);      // [4]
    volatile int*  cflag = (volatile int*)(fsm + OFF_FLAGS + 4);  // [4]

    const int tid = threadIdx.x;
    const int wid = tid >> 5, lid = tid & 31;
    const int u_base = blockIdx.x * 8;
    const int my_group = blockIdx.x >> 4;

    // ---- cooperative init (all 8 warps) ----
    // Wr fragments (16384 u32)
    for (int i = 0; i < 64; i++) {
        int lin = tid + i * NTHR;
        int reg = lin & 1;
        int ll  = (lin >> 1) & 31;
        int kcg = (lin >> 6) & 63;
        int q   = (lin >> 12) & 3;
        int lg = ll >> 2, lq = ll & 3;
        int k  = kcg * 16 + 2 * lq + 8 * reg;
        int col = q * kU + u_base + lg;
        float v0 = Wr[(size_t)k * k4U + col];
        float v1 = Wr[(size_t)(k + 1) * k4U + col];
        Wr_f[((q * 64 + kcg) * 32 + ll) * 2 + reg] = pack_bf16(v0, v1);
    }
    // Wk HMMA fragments (1664 uint2, kcg < 13)
    for (int i = 0; i < 7; i++) {
        int lin = tid + i * NTHR;
        if (lin < KHG * 4 * 32) {
            int lane = lin & 31;
            int nt   = (lin >> 5) & 3;
            int kcg  = lin >> 7;
            int gcol = nt * kU + u_base + (lane >> 2);
            int k2   = kcg * 16 + 2 * (lane & 3);
            uint2 bv;
            bv.x = pack_bf16(Wk[(size_t)k2 * k4U + gcol],
                             Wk[(size_t)(k2 + 1) * k4U + gcol]);
            bv.y = pack_bf16(Wk[(size_t)(k2 + 8) * k4U + gcol],
                             Wk[(size_t)(k2 + 9) * k4U + gcol]);
            Wk_f[(kcg * 4 + nt) * 32 + lane] = bv;
        }
    }
    // Wk fp32 for FFMA part: wk_s[k][qd][nt*2+e] = Wk[KH+k][nt*kU+u_base+2qd+e]
    for (int i = 0; i < KFF * 32 / NTHR; i++) {
        int lin = tid + i * NTHR;            // KFF*32 = 9728, exact multiple
        int e8 = lin & 7;
        int qd = (lin >> 3) & 3;
        int k  = lin >> 5;
        wk_s[lin] = Wk[(size_t)(KH + k) * k4U + (e8 >> 1) * kU + u_base +
                       2 * qd + (e8 & 1)];
    }
    if (tid < 32) bia_s[tid] = bias[(tid >> 3) * kU + u_base + (tid & 7)];
    if (tid < 4) { pflag[tid] = 0; cflag[tid] = 0; }
    __syncthreads();

    if (wid >= 4) {
        // ================= PRODUCER (warps 4-7) =================
        const int pw = wid - 4;              // M-subtile (16 batch rows)
        const int r  = pw * 16 + (lid >> 2);
        const int qd = lid & 3;
        const int cl = 2 * qd;
        const float* wkq = wk_s + qd * 8;    // row stride 32 floats

        for (int tp = 0; tp < kT; tp++) {
            const int s = tp & 3;
            if (tp >= 4) {
                while (cflag[s] < tp - 3) { }
                __threadfence_block();
            }
            float cacc[4][4];
#pragma unroll
            for (int nt = 0; nt < 4; nt++)
#pragma unroll
                for (int k = 0; k < 4; k++) cacc[nt][k] = 0.f;

            // ---- HMMA part: kcg 0..12 ----
            const uint4* Ap = g_xf + (size_t)tp * 4096 + pw * 32 + lid;
            uint4 pbuf[4];
#pragma unroll
            for (int i = 0; i < 4; i++) pbuf[i] = __ldcg(Ap + i * 128);
#pragma unroll
            for (int kcg = 0; kcg < KHG; kcg++) {
                uint4 a = pbuf[kcg & 3];
                if (kcg < KHG - 4) pbuf[kcg & 3] = __ldcg(Ap + (kcg + 4) * 128);
#pragma unroll
                for (int nt = 0; nt < 4; nt++) {
                    uint2 bv = Wk_f[(kcg * 4 + nt) * 32 + lid];
                    mma_bf16(cacc[nt], a.x, a.y, a.z, a.w, bv.x, bv.y);
                }
            }

            // ---- FFMA part: k in [KH, 512) ----
            const uint4* xr0 = (const uint4*)(g_xl + ((size_t)tp * 64 + r) * kF + KH);
            const uint4* xr1 = (const uint4*)(g_xl + ((size_t)tp * 64 + r + 8) * kF + KH);
            uint4 u0 = xr0[0], u1 = xr1[0];
#pragma unroll 2
            for (int kb = 0; kb < KFF4; kb++) {
                uint4 c0 = u0, c1 = u1;
                if (kb < KFF4 - 1) { u0 = xr0[kb + 1]; u1 = xr1[kb + 1]; }
                float xa[8], xb[8];
                xa[0] = bf_lo(c0.x); xa[1] = bf_hi(c0.x);
                xa[2] = bf_lo(c0.y); xa[3] = bf_hi(c0.y);
                xa[4] = bf_lo(c0.z); xa[5] = bf_hi(c0.z);
                xa[6] = bf_lo(c0.w); xa[7] = bf_hi(c0.w);
                xb[0] = bf_lo(c1.x); xb[1] = bf_hi(c1.x);
                xb[2] = bf_lo(c1.y); xb[3] = bf_hi(c1.y);
                xb[4] = bf_lo(c1.z); xb[5] = bf_hi(c1.z);
                xb[6] = bf_lo(c1.w); xb[7] = bf_hi(c1.w);
#pragma unroll
                for (int kk = 0; kk < 8; kk++) {
                    const float4* wrow =
                        (const float4*)(wkq + (kb * 8 + kk) * 32);
                    float4 w0 = wrow[0];
                    float4 w1 = wrow[1];
                    float va = xa[kk], vb = xb[kk];
                    cacc[0][0] = fmaf(va, w0.x, cacc[0][0]);
                    cacc[0][1] = fmaf(va, w0.y, cacc[0][1]);
                    cacc[0][2] = fmaf(vb, w0.x, cacc[0][2]);
                    cacc[0][3] = fmaf(vb, w0.y, cacc[0][3]);
                    cacc[1][0] = fmaf(va, w0.z, cacc[1][0]);
                    cacc[1][1] = fmaf(va, w0.w, cacc[1][1]);
                    cacc[1][2] = fmaf(vb, w0.z, cacc[1][2]);
                    cacc[1][3] = fmaf(vb, w0.w, cacc[1][3]);
                    cacc[2][0] = fmaf(va, w1.x, cacc[2][0]);
                    cacc[2][1] = fmaf(va, w1.y, cacc[2][1]);
                    cacc[2][2] = fmaf(vb, w1.x, cacc[2][2]);
                    cacc[2][3] = fmaf(vb, w1.y, cacc[2][3]);
                    cacc[3][0] = fmaf(va, w1.z, cacc[3][0]);
                    cacc[3][1] = fmaf(va, w1.w, cacc[3][1]);
                    cacc[3][2] = fmaf(vb, w1.z, cacc[3][2]);
                    cacc[3][3] = fmaf(vb, w1.w, cacc[3][3]);
                }
            }

            // epilogue: bias + ring store
            float* rs = ring + (size_t)s * 64 * 34;
#pragma unroll
            for (int nt = 0; nt < 4; nt++) {
                int col = nt * 8 + cl;
                float bx = bia_s[col], by = bia_s[col + 1];
                float2 lo = make_float2(cacc[nt][0] + bx, cacc[nt][1] + by);
                float2 hi = make_float2(cacc[nt][2] + bx, cacc[nt][3] + by);
                *(float2*)&rs[(r)     * 34 + col] = lo;
                *(float2*)&rs[(r + 8) * 34 + col] = hi;
            }
            __threadfence_block();
            bar_named(3, 128);
            if (tid == 128) pflag[s] = tp + 1;
        }
    } else {
        // ================= CONSUMER (warps 0-3) =================
        const int w = wid, l = lid;
        const int grp = l >> 2, qd = l & 3;
        const int b0 = w * 16 + grp;         // batch rows b0, b0+8
        const int j0 = 2 * qd;               // units j0, j0+1
        const int kcg_w = blockIdx.x >> 1;
        const int hi_w  = blockIdx.x & 1;

        float cst[4] = {0.f, 0.f, 0.f, 0.f};

        for (int t = 0; t < kT; t++) {
            const uint4* Ag = (const uint4*)(g_h + (size_t)(t & 1) * 32768);
            uint32_t*  hwrt = g_h + (size_t)((t + 1) & 1) * 32768;

            unsigned tgt = 16u * (unsigned)t;
            unsigned rdy = (t == 0) ? 0xffffffffu : 0u;
            const int g0 = my_group;
            while (!((rdy >> g0) & 1u)) rdy = poll_groups(l, tgt, rdy);

            float acc[4][2][4];
#pragma unroll
            for (int q = 0; q < 4; q++)
#pragma unroll
                for (int p = 0; p < 2; p++)
#pragma unroll
                    for (int k = 0; k < 4; k++) acc[q][p][k] = 0.f;

            uint4 abuf[8];
#pragma unroll
            for (int i = 0; i < 8; i++)
                abuf[i] = __ldcg(Ag + (8 * g0 + i) * 128 + tid);

            for (int ch = 0; ch < 8; ch++) {
                const int g  = (ch + my_group) & 7;
                const int gn = (g + 1) & 7;
                if (ch < 7)
                    while (!((rdy >> gn) & 1u)) rdy = poll_groups(l, tgt, rdy);
#pragma unroll
                for (int k8 = 0; k8 < 8; k8++) {
                    uint4 a = abuf[k8];
                    if (ch < 7) abuf[k8] = __ldcg(Ag + (8 * gn + k8) * 128 + tid);
                    int kcg = 8 * g + k8;
#pragma unroll
                    for (int q = 0; q < 4; q++) {
                        uint2 bv = *(const uint2*)&Wr_f[((q * 64 + kcg) * 32 + l) * 2];
                        mma_bf16(acc[q][k8 & 1], a.x, a.y, a.z, a.w, bv.x, bv.y);
                    }
                }
            }

            // xz from SMEM ring (producer runs ahead; wait usually instant)
            const int s = t & 3;
            while (pflag[s] < t + 1) { }
            __threadfence_block();
            const float* rs = ring + (size_t)s * 64 * 34;
            float2 xz[2][4];
#pragma unroll
            for (int r2 = 0; r2 < 2; r2++)
#pragma unroll
                for (int q = 0; q < 4; q++)
                    xz[r2][q] = *(const float2*)&rs[(b0 + 8 * r2) * 34 + q * 8 + j0];

            // gate phase (registers only)
#pragma unroll
            for (int r2 = 0; r2 < 2; r2++) {
                float hv[2];
#pragma unroll
                for (int d = 0; d < 2; d++) {
                    int idx = 2 * r2 + d;
                    float zi = acc[0][0][idx] + acc[0][1][idx] + (d ? xz[r2][0].y : xz[r2][0].x);
                    float zf = acc[1][0][idx] + acc[1][1][idx] + (d ? xz[r2][1].y : xz[r2][1].x);
                    float zg = acc[2][0][idx] + acc[2][1][idx] + (d ? xz[r2][2].y : xz[r2][2].x);
                    float zo = acc[3][0][idx] + acc[3][1][idx] + (d ? xz[r2][3].y : xz[r2][3].x);
                    float ig = sigmoid_fast(zi);
                    float fg = sigmoid_fast(zf);
                    float gg = tanh_fast(zg);
                    float og = sigmoid_fast(zo);
                    float cv = fg * cst[idx] + ig * gg;
                    cst[idx] = cv;
                    hv[d] = og * tanh_fast(cv);
                }
                hwrt[(kcg_w * 128 + tid) * 4 + 2 * hi_w + r2] = pack_bf16(hv[0], hv[1]);
            }

            // publish h + free ring stage
            __threadfence();
            bar_named(2, 128);
            if (tid == 0) {
                atomicAdd(&g_cnt[my_group * 32], 1u);
                cflag[s] = t + 1;
            }
        }
    }
}

// ---------------------------------------------------------------------------
// Kernel 3: logits = h_last @ Wd + bd; softmax per row (permuted bf16 buf 0)
// ---------------------------------------------------------------------------
__device__ __forceinline__ float h_read_b0(int b, int u) {
    uint32_t v = g_h[((u >> 4) * 128 + (b >> 4) * 32 + (b & 7) * 4 + ((u & 7) >> 1)) * 4
                     + 2 * ((u >> 3) & 1) + ((b >> 3) & 1)];
    return __uint_as_float((u & 1) ? (v & 0xffff0000u) : (v << 16));
}

__global__ __launch_bounds__(256) void dense_softmax_kernel(
    const float* __restrict__ Wd, const float* __restrict__ bd,
    float* __restrict__ out) {
    __shared__ float hrow[kU];
    __shared__ float red[256];

    const int b   = blockIdx.x;
    const int tid = threadIdx.x;
    for (int u = tid; u < kU; u += 256) hrow[u] = h_read_b0(b, u);
    __syncthreads();

    float acc[4] = {0.f, 0.f, 0.f, 0.f};
    const int j0 = tid * 4;
    const bool active = (j0 < kC);
    if (active) {
        const float* wp = Wd + j0;
#pragma unroll 4
        for (int k = 0; k < kU; k++) {
            float4 wv = *(const float4*)(wp + (size_t)k * kC);
            float  hk = hrow[k];
            acc[0] = fmaf(hk, wv.x, acc[0]);
            acc[1] = fmaf(hk, wv.y, acc[1]);
            acc[2] = fmaf(hk, wv.z, acc[2]);
            acc[3] = fmaf(hk, wv.w, acc[3]);
        }
        float4 bv = *(const float4*)&bd[j0];
        acc[0] += bv.x; acc[1] += bv.y; acc[2] += bv.z; acc[3] += bv.w;
    }

    float m = active ? fmaxf(fmaxf(acc[0], acc[1]), fmaxf(acc[2], acc[3]))
                     : -INFINITY;
    red[tid] = m;
    __syncthreads();
    for (int s = 128; s > 0; s >>= 1) {
        if (tid < s) red[tid] = fmaxf(red[tid], red[tid + s]);
        __syncthreads();
    }
    float mx = red[0];
    __syncthreads();

    float e[4] = {0.f, 0.f, 0.f, 0.f};
    float psum = 0.f;
    if (active) {
#pragma unroll
        for (int cc = 0; cc < 4; cc++) { e[cc] = expf(acc[cc] - mx); psum += e[cc]; }
    }
    red[tid] = psum;
    __syncthreads();
    for (int s = 128; s > 0; s >>= 1) {
        if (tid < s) red[tid] += red[tid + s];
        __syncthreads();
    }
    float inv = 1.f / red[0];
    if (active) {
#pragma unroll
        for (int cc = 0; cc < 4; cc++) out[(size_t)b * kC + j0 + cc] = e[cc] * inv;
    }
}

// ---------------------------------------------------------------------------
// Launch
// ---------------------------------------------------------------------------
extern "C" void kernel_launch(void* const* d_in, const int* in_sizes, int n_in,
                              void* d_out, int out_size) {
    const float* x    = (const float*)d_in[0];
    const float* Wk   = (const float*)d_in[1];
    const float* Wr   = (const float*)d_in[2];
    const float* bias = (const float*)d_in[3];
    const float* Wd   = (const float*)d_in[4];
    const float* bd   = (const float*)d_in[5];
    float* out = (float*)d_out;

    const int smem_bytes = SMEM_U32 * (int)sizeof(uint32_t);   // 152736
    cudaFuncSetAttribute(lstm_fused, cudaFuncAttributeMaxDynamicSharedMemorySize,
                         smem_bytes);

    reset_kernel<<<64, 256>>>();
    permute_x<<<(int)((size_t)kT * 4096 / 256), 256>>>(x);
    permute_lin<<<(int)((size_t)kT * 64 * kF / 8 / 256), 256>>>(x);
    lstm_fused<<<NCTA, NTHR, smem_bytes>>>(Wr, Wk, bias);
    dense_softmax_kernel<<<kB, 256>>>(Wd, bd, out);
}